// round 11
// baseline (speedup 1.0000x reference)
#include <cuda_runtime.h>
#include <cuda_fp16.h>
#include <math.h>
#include <stdint.h>

// ---------------------------------------------------------------------------
// VectorQuantizer for GB300 (sm_103a, built as plain sm_103 -> no tcgen05)
//   z:            [32,4096,256] f32  -> N=131072 tokens, D=256
//   embed_weight: [1024,256]    f32  -> K=1024 codes
// Outputs (f32): z_q_st [N*256], loss, perplexity, indices [N] (as float)
//
// Pipeline:
//   prep_cb:  normalize codebook -> g_bn (f32) + g_bh (fp16); zero stats
//   prep_zn:  normalize z per token -> g_zh (fp16)
//   vq_mma:   fp16 mma.sync argmax-GEMM, fp32 accum; per token: top-4
//             candidate indices + gap guard (gap12 < TAU -> flag)
//   vq_rescue: exact fp32 rescoring of <=4 candidates per flagged token
//   vq_out:   indices -> out, histogram, gather + STE + loss partials
//   finalize: loss & perplexity scalars
// ---------------------------------------------------------------------------

#define D_DIM 256
#define NTOK  131072
#define NCODE 1024
#define NBLK  (NTOK / 128)
#define TAU   7.5e-4f

// ---- static device scratch ----
__device__ __half g_zh[(size_t)NTOK * D_DIM];
__device__ __half g_bh[NCODE * D_DIM];
__device__ float  g_bn[NCODE * D_DIM];
__device__ int    g_idx[NTOK];
__device__ int    g_cand[(size_t)NTOK * 4];
__device__ int    g_flags[NTOK];
__device__ int    g_flagcnt;
__device__ int    g_counts[NCODE];
__device__ float  g_partial[NBLK];

// ---- helpers ----
__device__ __forceinline__ void cp16(void* dst_smem, const void* src_gmem) {
    unsigned sdst = (unsigned)__cvta_generic_to_shared(dst_smem);
    asm volatile("cp.async.cg.shared.global [%0], [%1], 16;\n" :: "r"(sdst), "l"(src_gmem));
}
__device__ __forceinline__ void cp_commit() {
    asm volatile("cp.async.commit_group;\n" ::: "memory");
}
__device__ __forceinline__ void mma16816(float* d, const uint32_t* a,
                                         uint32_t b0, uint32_t b1) {
    asm volatile(
        "mma.sync.aligned.m16n8k16.row.col.f32.f16.f16.f32 "
        "{%0,%1,%2,%3}, {%4,%5,%6,%7}, {%8,%9}, {%0,%1,%2,%3};"
        : "+f"(d[0]), "+f"(d[1]), "+f"(d[2]), "+f"(d[3])
        : "r"(a[0]), "r"(a[1]), "r"(a[2]), "r"(a[3]), "r"(b0), "r"(b1));
}

// ---------------- prep: codebook ----------------
__global__ void prep_cb(const float* __restrict__ w) {
    int k = blockIdx.x;
    int tid = threadIdx.x;   // 256 = D
    float v = w[(size_t)k * D_DIM + tid];
    float s = v * v;
    #pragma unroll
    for (int o = 16; o; o >>= 1) s += __shfl_xor_sync(0xffffffffu, s, o);
    __shared__ float ws[8];
    int lane = tid & 31, warp = tid >> 5;
    if (lane == 0) ws[warp] = s;
    __syncthreads();
    if (tid == 0) {
        float t = 0.f;
        #pragma unroll
        for (int i = 0; i < 8; i++) t += ws[i];
        ws[0] = t;
    }
    __syncthreads();
    float bn = v / fmaxf(sqrtf(ws[0]), 1e-12f);
    size_t o = (size_t)k * D_DIM + tid;
    g_bn[o] = bn;
    g_bh[o] = __float2half_rn(bn);
    if (tid == 0) g_counts[k] = 0;
    if (k == 0 && tid == 0) g_flagcnt = 0;
}

// ---------------- prep: z normalize + fp16 ----------------
__global__ __launch_bounds__(256)
void prep_zn(const float* __restrict__ z) {
    const int warp = threadIdx.x >> 5, lane = threadIdx.x & 31;
    const size_t tok = (size_t)blockIdx.x * 8 + warp;
    const float4* zr = (const float4*)(z + tok * D_DIM);
    float4 v0 = zr[lane], v1 = zr[lane + 32];
    float s = v0.x * v0.x + v0.y * v0.y + v0.z * v0.z + v0.w * v0.w
            + v1.x * v1.x + v1.y * v1.y + v1.z * v1.z + v1.w * v1.w;
    #pragma unroll
    for (int o = 16; o; o >>= 1) s += __shfl_xor_sync(0xffffffffu, s, o);
    float inv = 1.0f / fmaxf(sqrtf(s), 1e-12f);
    __half2* oh = (__half2*)(g_zh + tok * D_DIM);
    oh[lane * 2]      = __floats2half2_rn(v0.x * inv, v0.y * inv);
    oh[lane * 2 + 1]  = __floats2half2_rn(v0.z * inv, v0.w * inv);
    oh[64 + lane * 2]     = __floats2half2_rn(v1.x * inv, v1.y * inv);
    oh[64 + lane * 2 + 1] = __floats2half2_rn(v1.z * inv, v1.w * inv);
}

// ---------------- main: fp16 mma argmax-GEMM ----------------
// smem: A 128 rows x 132 words (pad 4) = 67584B; B double buffer 2x67584B
#define AROW 132
#define TILE_BYTES (128 * AROW * 4)
#define SMEM_MAIN (3 * TILE_BYTES)     // 202752

__global__ __launch_bounds__(256, 1)
void vq_mma() {
    extern __shared__ __align__(16) char smem[];
    uint32_t* As = (uint32_t*)smem;
    uint32_t* Bs = (uint32_t*)(smem + TILE_BYTES);

    const int tid = threadIdx.x;
    const int lane = tid & 31, warp = tid >> 5;
    const int wm = warp >> 1, wn = warp & 1;
    const int g = lane >> 2, kq = lane & 3;
    const int blk = blockIdx.x;

    // ---- prologue: load A (fp16 tokens) + B tile 0 ----
    {
        const __half* zsrc = g_zh + (size_t)blk * 128 * D_DIM;
        #pragma unroll
        for (int j = 0; j < 16; j++) {
            int m = tid + j * 256;
            int row = m >> 5, c = m & 31;
            cp16((char*)As + row * 528 + c * 16, zsrc + row * 256 + c * 8);
        }
        const __half* bsrc = g_bh;
        #pragma unroll
        for (int j = 0; j < 16; j++) {
            int m = tid + j * 256;
            int row = m >> 5, c = m & 31;
            cp16((char*)Bs + row * 528 + c * 16, bsrc + row * 256 + c * 8);
        }
        cp_commit();
        asm volatile("cp.async.wait_group 0;\n" ::: "memory");
        __syncthreads();
    }

    float best[4], best2[4];
    int   bidx[4], bidx2[4];
    #pragma unroll
    for (int i = 0; i < 4; i++) {
        best[i] = -3.4e38f; best2[i] = -3.4e38f; bidx[i] = 0; bidx2[i] = 0;
    }

    for (int ct = 0; ct < 8; ct++) {
        uint32_t* Bc = Bs + (ct & 1) * (TILE_BYTES / 4);

        // prefetch next B tile into the other buffer (its consumers synced last iter)
        if (ct < 7) {
            const __half* bsrc = g_bh + (size_t)(ct + 1) * 128 * D_DIM;
            char* dst = (char*)Bs + ((ct + 1) & 1) * TILE_BYTES;
            #pragma unroll
            for (int j = 0; j < 16; j++) {
                int m = tid + j * 256;
                int row = m >> 5, c = m & 31;
                cp16(dst + row * 528 + c * 16, bsrc + row * 256 + c * 8);
            }
            cp_commit();
        }

        float acc[2][8][4];
        #pragma unroll
        for (int mi = 0; mi < 2; mi++)
            #pragma unroll
            for (int ni = 0; ni < 8; ni++)
                #pragma unroll
                for (int c = 0; c < 4; c++) acc[mi][ni][c] = 0.f;

        #pragma unroll
        for (int ks = 0; ks < 16; ks++) {
            uint32_t a[2][4];
            #pragma unroll
            for (int mi = 0; mi < 2; mi++) {
                int r0 = (wm * 32 + mi * 16 + g) * AROW;
                int r1 = r0 + 8 * AROW;
                int w0 = ks * 8 + kq;
                a[mi][0] = As[r0 + w0];
                a[mi][1] = As[r1 + w0];
                a[mi][2] = As[r0 + w0 + 4];
                a[mi][3] = As[r1 + w0 + 4];
            }
            #pragma unroll
            for (int ni = 0; ni < 8; ni++) {
                int br = (wn * 64 + ni * 8 + g) * AROW + ks * 8 + kq;
                uint32_t b0 = Bc[br], b1 = Bc[br + 4];
                mma16816(acc[0][ni], a[0], b0, b1);
                mma16816(acc[1][ni], a[1], b0, b1);
            }
        }

        // fold this tile into running top-2 (value+index) per row instance
        #pragma unroll
        for (int mi = 0; mi < 2; mi++)
            #pragma unroll
            for (int h = 0; h < 2; h++) {
                int ri = mi * 2 + h;
                #pragma unroll
                for (int ni = 0; ni < 8; ni++)
                    #pragma unroll
                    for (int c = 0; c < 2; c++) {
                        float v = acc[mi][ni][h * 2 + c];
                        int cb = ct * 128 + wn * 64 + ni * 8 + kq * 2 + c;
                        if (v > best[ri]) {
                            best2[ri] = best[ri]; bidx2[ri] = bidx[ri];
                            best[ri] = v; bidx[ri] = cb;
                        } else if (v > best2[ri]) {
                            best2[ri] = v; bidx2[ri] = cb;
                        }
                    }
            }

        if (ct < 7) {
            asm volatile("cp.async.wait_group 0;\n" ::: "memory");
            __syncthreads();
        }
    }

    // ---- cross-thread merge: top-4 candidates per token (8 threads/token) ----
    __syncthreads();
    float* rb  = (float*)smem;            // [128][8] best
    float* rb2 = rb + 1024;               // [128][8] best2
    int*   rix  = (int*)(rb2 + 1024);     // [128][8] idx
    int*   rix2 = rix + 1024;             // [128][8] idx2
    const int slot = wn * 4 + kq;
    #pragma unroll
    for (int ri = 0; ri < 4; ri++) {
        int row = wm * 32 + (ri >> 1) * 16 + (ri & 1) * 8 + g;
        rb  [row * 8 + slot] = best[ri];
        rb2 [row * 8 + slot] = best2[ri];
        rix [row * 8 + slot] = bidx[ri];
        rix2[row * 8 + slot] = bidx2[ri];
    }
    __syncthreads();
    if (tid < 128) {
        float v[16]; int ix[16];
        #pragma unroll
        for (int s = 0; s < 8; s++) {
            v[s]     = rb [tid * 8 + s];  ix[s]     = rix [tid * 8 + s];
            v[8 + s] = rb2[tid * 8 + s];  ix[8 + s] = rix2[tid * 8 + s];
        }
        int   csel[4];
        float cval[4];
        #pragma unroll
        for (int j = 0; j < 4; j++) {
            float bv = -3.4e38f; int bi = 0x7fffffff, bs = 0;
            #pragma unroll
            for (int s = 0; s < 16; s++) {
                if (v[s] > bv || (v[s] == bv && ix[s] < bi)) {
                    bv = v[s]; bi = ix[s]; bs = s;
                }
            }
            csel[j] = bi; cval[j] = bv;
            v[bs] = -3.4e38f;
        }
        int tok = blk * 128 + tid;
        g_idx[tok] = csel[0];
        g_cand[(size_t)tok * 4 + 0] = csel[0];
        g_cand[(size_t)tok * 4 + 1] = csel[1];
        g_cand[(size_t)tok * 4 + 2] = csel[2];
        g_cand[(size_t)tok * 4 + 3] = csel[3];
        if (cval[0] - cval[1] < TAU) {
            int sl = atomicAdd(&g_flagcnt, 1);
            g_flags[sl] = tok;
        }
    }
}

// ---------------- rescue: exact fp32 rescore of <=4 candidates ----------------
// One warp per flagged token. Each lane owns 8 dims of the z row.
__global__ __launch_bounds__(256)
void vq_rescue(const float* __restrict__ z) {
    const int lane = threadIdx.x & 31, warp = threadIdx.x >> 5;
    const int nf = g_flagcnt;
    for (int f = blockIdx.x * 8 + warp; f < nf; f += gridDim.x * 8) {
        const int tok = g_flags[f];
        const float4* zr = (const float4*)(z + (size_t)tok * D_DIM) + lane * 2;
        float4 z0 = zr[0], z1 = zr[1];

        float bestv = -3.4e38f; int besti = 0x7fffffff;
        #pragma unroll
        for (int j = 0; j < 4; j++) {
            int c = g_cand[(size_t)tok * 4 + j];
            const float4* cr = (const float4*)(g_bn + (size_t)c * D_DIM) + lane * 2;
            float4 c0 = cr[0], c1 = cr[1];
            float s = z0.x * c0.x + z0.y * c0.y + z0.z * c0.z + z0.w * c0.w
                    + z1.x * c1.x + z1.y * c1.y + z1.z * c1.z + z1.w * c1.w;
            #pragma unroll
            for (int o = 16; o; o >>= 1) s += __shfl_xor_sync(0xffffffffu, s, o);
            if (s > bestv || (s == bestv && c < besti)) { bestv = s; besti = c; }
        }
        if (lane == 0) g_idx[tok] = besti;
    }
}

// ---------------- output pass: idx -> out, hist, gather + STE + loss ----------------
__global__ __launch_bounds__(256)
void vq_out(const float* __restrict__ z, const float* __restrict__ w,
            float* __restrict__ out_zq, float* __restrict__ out_idx) {
    __shared__ int   idx_s[128];
    __shared__ float red_s[8];
    const int tid = threadIdx.x;
    const int blk = blockIdx.x;
    const int lane = tid & 31, warp = tid >> 5;

    if (tid < 128) {
        int gi = g_idx[blk * 128 + tid];
        idx_s[tid] = gi;
        out_idx[blk * 128 + tid] = (float)gi;
        atomicAdd(&g_counts[gi], 1);
    }
    __syncthreads();

    float ls = 0.f;
    {
        const int t = tid >> 1, dh = tid & 1;
        const int gi = idx_s[t];
        const float4* wrow = (const float4*)(w + (size_t)gi * D_DIM + dh * 128);
        const float4* zrow = (const float4*)(z + ((size_t)blk * 128 + t) * D_DIM + dh * 128);
        float4* orow = (float4*)(out_zq + ((size_t)blk * 128 + t) * D_DIM + dh * 128);
        #pragma unroll
        for (int i = 0; i < 32; i++) {
            float4 q = wrow[i];
            float4 zv = zrow[i];
            float e0 = q.x - zv.x, e1 = q.y - zv.y, e2 = q.z - zv.z, e3 = q.w - zv.w;
            float4 o; o.x = zv.x + e0; o.y = zv.y + e1; o.z = zv.z + e2; o.w = zv.w + e3;
            orow[i] = o;
            ls += e0 * e0 + e1 * e1 + e2 * e2 + e3 * e3;
        }
    }
    #pragma unroll
    for (int o = 16; o; o >>= 1) ls += __shfl_xor_sync(0xffffffffu, ls, o);
    if (lane == 0) red_s[warp] = ls;
    __syncthreads();
    if (tid == 0) {
        float t = 0.f;
        #pragma unroll
        for (int i = 0; i < 8; i++) t += red_s[i];
        g_partial[blk] = t;
    }
}

// ---------------- finalize: loss + perplexity ----------------
__global__ void finalize_kernel(float* __restrict__ out_sc, int N, int K, int nblk) {
    __shared__ float sh[1024];
    int tid = threadIdx.x;
    float s = (tid < nblk) ? g_partial[tid] : 0.f;
    sh[tid] = s;
    __syncthreads();
    for (int st = 512; st; st >>= 1) {
        if (tid < st) sh[tid] += sh[tid + st];
        __syncthreads();
    }
    float S = sh[0];
    __syncthreads();
    float e = 0.f;
    if (tid < K) {
        float p = (float)g_counts[tid] / (float)N;
        e = p * logf(p + 1e-10f);
    }
    sh[tid] = e;
    __syncthreads();
    for (int st = 512; st; st >>= 1) {
        if (tid < st) sh[tid] += sh[tid + st];
        __syncthreads();
    }
    if (tid == 0) {
        out_sc[0] = 1.25f * S / ((float)N * (float)D_DIM);
        out_sc[1] = expf(-sh[0]);
    }
}

// ---------------- launch ----------------
extern "C" void kernel_launch(void* const* d_in, const int* in_sizes, int n_in,
                              void* d_out, int out_size) {
    const float* z = (const float*)d_in[0];
    const float* w = (const float*)d_in[1];
    const int n_z = in_sizes[0];          // N * 256
    const int N = n_z / D_DIM;
    const int nblk = N / 128;

    float* out = (float*)d_out;
    float* out_zq  = out;
    float* out_sc  = out + n_z;
    float* out_idx = out + n_z + 2;

    prep_cb<<<NCODE, 256>>>(w);
    prep_zn<<<N / 8, 256>>>(z);

    cudaFuncSetAttribute(vq_mma, cudaFuncAttributeMaxDynamicSharedMemorySize, SMEM_MAIN);
    vq_mma<<<nblk, 256, SMEM_MAIN>>>();

    vq_rescue<<<128, 256>>>(z);
    vq_out<<<nblk, 256>>>(z, w, out_zq, out_idx);
    finalize_kernel<<<1, 1024>>>(out_sc, N, NCODE, nblk);
}